// round 6
// baseline (speedup 1.0000x reference)
#include <cuda_runtime.h>
#include <cuda_bf16.h>

// Problem constants (fixed by the reference).
#define BB   2
#define DD   96
#define HH   96
#define WW   96
#define CIN  16
#define COUT 32
#define NK   27
#define GRIDVOL (BB*DD*HH*WW)      // 1,769,472

#define NBIN  26                   // off-center offsets only (center handled in gather)
#define NCAP  32768                // max pairs per bin (expected ~23K worst case)
#define CHUNK 64                   // points per probe block
#define INVS  28                   // padded inverse-row stride (28 ints = 112B, 16B-aligned)

#define CONV_BLOCKS  592
#define CONV_THREADS 256
#define TOTW (CONV_BLOCKS*(CONV_THREADS/32))   // 4736 warps

typedef unsigned long long u64;

// Scratch (static __device__ arrays: allocation-free).
__device__ int   g_grid[GRIDVOL];               // voxel -> point id, -1 empty
__device__ u64   g_wk2[NK * (CIN/2) * COUT];    // [k][ci2][co] packed f32x2
__device__ int   g_cnt[NBIN];                   // pairs per bin
__device__ int   g_pj[NBIN * NCAP];             // input point id per pair slot
__device__ float g_part[(long)NBIN * NCAP * COUT]; // per-pair partial outputs
__device__ int   g_ninv[200704 * INVS];         // per-point inverse slot list
__device__ int   g_ncnt[200704];                // per-point neighbor count

// ---------------------------------------------------------------------------
// Packed f32x2 helpers (sm_103a FFMA2 path).
__device__ __forceinline__ u64 fma2(u64 a, u64 b, u64 c) {
    u64 d; asm("fma.rn.f32x2 %0, %1, %2, %3;" : "=l"(d) : "l"(a), "l"(b), "l"(c));
    return d;
}
__device__ __forceinline__ u64 mul2(u64 a, u64 b) {
    u64 d; asm("mul.rn.f32x2 %0, %1, %2;" : "=l"(d) : "l"(a), "l"(b));
    return d;
}
__device__ __forceinline__ u64 add2(u64 a, u64 b) {
    u64 d; asm("add.rn.f32x2 %0, %1, %2;" : "=l"(d) : "l"(a), "l"(b));
    return d;
}
__device__ __forceinline__ float hsum2(u64 a) {
    unsigned lo, hi;
    asm("mov.b64 {%0, %1}, %2;" : "=r"(lo), "=r"(hi) : "l"(a));
    return __uint_as_float(lo) + __uint_as_float(hi);
}

// 16-channel dot product, packed: f = 4 x ulonglong2 (16 floats), w = 8 x u64.
__device__ __forceinline__ float dot16p(const ulonglong2& f0, const ulonglong2& f1,
                                        const ulonglong2& f2, const ulonglong2& f3,
                                        const u64* w) {
    u64 s0 = mul2(f0.x, w[0]);
    u64 s1 = mul2(f0.y, w[1]);
    s0 = fma2(f1.x, w[2], s0);
    s1 = fma2(f1.y, w[3], s1);
    s0 = fma2(f2.x, w[4], s0);
    s1 = fma2(f2.y, w[5], s1);
    s0 = fma2(f3.x, w[6], s0);
    s1 = fma2(f3.y, w[7], s1);
    return hsum2(add2(s0, s1));
}

// ---------------------------------------------------------------------------
__global__ void scatter_idx_kernel(const int4* __restrict__ idx, int n) {
    int p = blockIdx.x * blockDim.x + threadIdx.x;
    if (p < n) {
        int4 q = idx[p];  // b, z, y, x
        g_grid[((q.x * DD + q.y) * HH + q.z) * WW + q.w] = p;
    }
}

// conv_w [co][ci][kd][kh][kw] -> g_wk2[k][ci2][co]; also zeroes bin counters.
__global__ void repack_w_kernel(const float* __restrict__ w) {
    int t = blockIdx.x * blockDim.x + threadIdx.x;
    if (blockIdx.x == 0 && threadIdx.x < NBIN) g_cnt[threadIdx.x] = 0;
    if (t < NK * (CIN/2) * COUT) {
        int k   = t / ((CIN/2) * COUT);
        int r   = t % ((CIN/2) * COUT);
        int ci2 = r / COUT;
        int co  = r % COUT;
        float w0 = w[(co * CIN + 2*ci2    ) * NK + k];
        float w1 = w[(co * CIN + 2*ci2 + 1) * NK + k];
        g_wk2[t] = ((u64)__float_as_uint(w1) << 32) | __float_as_uint(w0);
    }
}

// ---------------------------------------------------------------------------
// Build 26 off-center pair lists + per-point inverse slot lists.
// Lane l (<26) probes offset kk = l<13 ? l : l+1. Per-point slot rank comes
// from ballot/popc (no atomics); global slots assigned at block flush.
__global__ __launch_bounds__(256)
void probe_kernel(const int4* __restrict__ idx, int n) {
    __shared__ int  scnt[NBIN];
    __shared__ int  sbase[NBIN];
    __shared__ int2 srec[NBIN * CHUNK];           // (j, p | pslot<<20)

    int tid = threadIdx.x, lane = tid & 31, warp = tid >> 5;
    if (tid < NBIN) scnt[tid] = 0;
    __syncthreads();

    int kk = lane < 13 ? lane : lane + 1;
    int dz = kk / 9 - 1, dy = (kk / 3) % 3 - 1, dx = kk % 3 - 1;
    int p0 = blockIdx.x * CHUNK + warp * (CHUNK / 8);

#pragma unroll
    for (int r = 0; r < CHUNK / 8; r++) {
        int p = p0 + r;
        int j = -1;
        if (p < n && lane < NBIN) {
            int4 q = __ldg(&idx[p]);
            int zz = q.y + dz, yy = q.z + dy, xx = q.w + dx;
            if ((unsigned)zz < (unsigned)DD &&
                (unsigned)yy < (unsigned)HH &&
                (unsigned)xx < (unsigned)WW) {
                j = __ldg(&g_grid[((q.x * DD + zz) * HH + yy) * WW + xx]);
            }
        }
        unsigned mask = __ballot_sync(0xffffffffu, j >= 0);
        if (p < n && lane == 0) g_ncnt[p] = __popc(mask);
        if (j >= 0) {
            int pslot = __popc(mask & ((1u << lane) - 1));
            int pos = atomicAdd(&scnt[lane], 1);
            srec[lane * CHUNK + pos] = make_int2(j, p | (pslot << 20));
        }
    }
    __syncthreads();
    if (tid < NBIN) sbase[tid] = atomicAdd(&g_cnt[tid], scnt[tid]);
    __syncthreads();
    for (int t = tid; t < NBIN * CHUNK; t += 256) {
        int b = t / CHUNK, i = t % CHUNK;
        if (i < scnt[b]) {
            int2 rec = srec[t];
            int s = sbase[b] + i;
            if (s < NCAP) {
                int p     = rec.y & 0xFFFFF;
                int pslot = rec.y >> 20;
                g_pj[b * NCAP + s]        = rec.x;
                g_ninv[p * INVS + pslot]  = b * NCAP + s;
            }
        }
    }
}

// ---------------------------------------------------------------------------
// Phase B: per-pair partial outputs, register weights, NO atomics.
// lane = output channel; plain coalesced STG per pair.
__global__ __launch_bounds__(256)
void pair_partial_kernel(const ulonglong2* __restrict__ feat2) {
    int lane = threadIdx.x & 31;
    int w = blockIdx.x * (CONV_THREADS / 32) + (threadIdx.x >> 5);
    int b = w % NBIN, slice = w / NBIN;
    int nwk = (TOTW - b + NBIN - 1) / NBIN;
    int kk = b < 13 ? b : b + 1;

    u64 wk[8];
#pragma unroll
    for (int i = 0; i < 8; i++) wk[i] = g_wk2[(kk * 8 + i) * COUT + lane];

    int cnt = min(g_cnt[b], NCAP);
    const int* pj = g_pj + b * NCAP;
    float* part = g_part + (long)b * NCAP * COUT;

    int chunk = (((cnt + nwk - 1) / nwk) + 3) & ~3;  // multiple of 4 (int4 align)
    int i0 = slice * chunk;
    int i1 = min(cnt, i0 + chunk);

    int i = i0;
    for (; i + 3 < i1; i += 4) {
        int4 jj = __ldg((const int4*)(pj + i));
        const ulonglong2* fa = feat2 + ((long)jj.x << 2);
        const ulonglong2* fb = feat2 + ((long)jj.y << 2);
        const ulonglong2* fc = feat2 + ((long)jj.z << 2);
        const ulonglong2* fd = feat2 + ((long)jj.w << 2);
        ulonglong2 a0 = __ldg(fa), a1 = __ldg(fa + 1),
                   a2 = __ldg(fa + 2), a3 = __ldg(fa + 3);
        ulonglong2 e0 = __ldg(fb), e1 = __ldg(fb + 1),
                   e2 = __ldg(fb + 2), e3 = __ldg(fb + 3);
        ulonglong2 c0 = __ldg(fc), c1 = __ldg(fc + 1),
                   c2 = __ldg(fc + 2), c3 = __ldg(fc + 3);
        ulonglong2 g0 = __ldg(fd), g1 = __ldg(fd + 1),
                   g2 = __ldg(fd + 2), g3 = __ldg(fd + 3);
        part[(long)(i + 0) * COUT + lane] = dot16p(a0, a1, a2, a3, wk);
        part[(long)(i + 1) * COUT + lane] = dot16p(e0, e1, e2, e3, wk);
        part[(long)(i + 2) * COUT + lane] = dot16p(c0, c1, c2, c3, wk);
        part[(long)(i + 3) * COUT + lane] = dot16p(g0, g1, g2, g3, wk);
    }
    for (; i < i1; i++) {
        int j = __ldg(&pj[i]);
        const ulonglong2* fa = feat2 + ((long)j << 2);
        ulonglong2 a0 = __ldg(fa), a1 = __ldg(fa + 1),
                   a2 = __ldg(fa + 2), a3 = __ldg(fa + 3);
        part[(long)i * COUT + lane] = dot16p(a0, a1, a2, a3, wk);
    }
}

// ---------------------------------------------------------------------------
// Phase C: per-point gather. center tap (register W13) + bias + partial sums.
// Warp per point, 2 points per iteration; NO atomics.
__global__ __launch_bounds__(256)
void gather_out_kernel(const ulonglong2* __restrict__ feat2,
                       const float* __restrict__ bias,
                       float* __restrict__ out, int n) {
    int lane = threadIdx.x & 31;
    int w = blockIdx.x * (CONV_THREADS / 32) + (threadIdx.x >> 5);
    u64 wk[8];
#pragma unroll
    for (int i = 0; i < 8; i++) wk[i] = g_wk2[(13 * 8 + i) * COUT + lane];
    float b0 = __ldg(&bias[lane]);

    int p = w * 2;
    const int stride = TOTW * 2;
    for (; p + 1 < n; p += stride) {
        int pA = p, pB = p + 1;
        const ulonglong2* fA = feat2 + ((long)pA << 2);
        const ulonglong2* fB = feat2 + ((long)pB << 2);
        ulonglong2 a0 = __ldg(fA), a1 = __ldg(fA + 1),
                   a2 = __ldg(fA + 2), a3 = __ldg(fA + 3);
        ulonglong2 e0 = __ldg(fB), e1 = __ldg(fB + 1),
                   e2 = __ldg(fB + 2), e3 = __ldg(fB + 3);
        int cA = __ldg(&g_ncnt[pA]);
        int cB = __ldg(&g_ncnt[pB]);
        int4 vA = __ldg((const int4*)(g_ninv + pA * INVS));
        int4 vB = __ldg((const int4*)(g_ninv + pB * INVS));

        float accA = b0 + dot16p(a0, a1, a2, a3, wk);
        float accB = b0 + dot16p(e0, e1, e2, e3, wk);

        float q0 = (cA > 0) ? __ldg(&g_part[(long)vA.x * COUT + lane]) : 0.0f;
        float q1 = (cA > 1) ? __ldg(&g_part[(long)vA.y * COUT + lane]) : 0.0f;
        float q2 = (cA > 2) ? __ldg(&g_part[(long)vA.z * COUT + lane]) : 0.0f;
        float q3 = (cA > 3) ? __ldg(&g_part[(long)vA.w * COUT + lane]) : 0.0f;
        float r0 = (cB > 0) ? __ldg(&g_part[(long)vB.x * COUT + lane]) : 0.0f;
        float r1 = (cB > 1) ? __ldg(&g_part[(long)vB.y * COUT + lane]) : 0.0f;
        float r2 = (cB > 2) ? __ldg(&g_part[(long)vB.z * COUT + lane]) : 0.0f;
        float r3 = (cB > 3) ? __ldg(&g_part[(long)vB.w * COUT + lane]) : 0.0f;
        accA += (q0 + q1) + (q2 + q3);
        accB += (r0 + r1) + (r2 + r3);

        for (int s = 4; s < cA; s++) {
            int a = __ldg(&g_ninv[pA * INVS + s]);
            accA += __ldg(&g_part[(long)a * COUT + lane]);
        }
        for (int s = 4; s < cB; s++) {
            int a = __ldg(&g_ninv[pB * INVS + s]);
            accB += __ldg(&g_part[(long)a * COUT + lane]);
        }
        out[(long)pA * COUT + lane] = accA;
        out[(long)pB * COUT + lane] = accB;
    }
    if (p < n) {
        const ulonglong2* fA = feat2 + ((long)p << 2);
        ulonglong2 a0 = __ldg(fA), a1 = __ldg(fA + 1),
                   a2 = __ldg(fA + 2), a3 = __ldg(fA + 3);
        int cA = __ldg(&g_ncnt[p]);
        float acc = b0 + dot16p(a0, a1, a2, a3, wk);
        for (int s = 0; s < cA; s++) {
            int a = __ldg(&g_ninv[p * INVS + s]);
            acc += __ldg(&g_part[(long)a * COUT + lane]);
        }
        out[(long)p * COUT + lane] = acc;
    }
}

// ---------------------------------------------------------------------------
extern "C" void kernel_launch(void* const* d_in, const int* in_sizes, int n_in,
                              void* d_out, int out_size) {
    const float* feat = (const float*)d_in[0];   // [n,16] f32
    const int*   idx  = (const int*)d_in[1];     // [n,4]  i32
    const float* w    = (const float*)d_in[2];   // [32,16,3,3,3] f32
    const float* bias = (const float*)d_in[3];   // [32] f32
    int n = in_sizes[1] / 4;

    void* gptr = nullptr; cudaGetSymbolAddress(&gptr, g_grid);
    cudaMemsetAsync(gptr, 0xFF, sizeof(int) * (size_t)GRIDVOL);          // act 1

    scatter_idx_kernel<<<(n + 255) / 256, 256>>>((const int4*)idx, n);   // act 2
    repack_w_kernel<<<(NK * (CIN/2) * COUT + 255) / 256, 256>>>(w);      // act 3
    probe_kernel<<<(n + CHUNK - 1) / CHUNK, 256>>>((const int4*)idx, n); // act 4
    pair_partial_kernel<<<CONV_BLOCKS, CONV_THREADS>>>(
        (const ulonglong2*)feat);                                        // act 5
    gather_out_kernel<<<CONV_BLOCKS, CONV_THREADS>>>(
        (const ulonglong2*)feat, bias, (float*)d_out, n);                // act 6 (profiled)
}

// round 7
// speedup vs baseline: 1.7474x; 1.7474x over previous
#include <cuda_runtime.h>
#include <cuda_bf16.h>

// Problem constants (fixed by the reference).
#define BB   2
#define DD   96
#define HH   96
#define WW   96
#define CIN  16
#define COUT 32
#define NK   27
#define GRIDVOL (BB*DD*HH*WW)      // 1,769,472
#define NPTMAX 200704              // padded point capacity

#define NBIN  26                   // 27 offsets minus the center (k=13)
#define NCAP  32768
#define CHUNK 64

#define CONV_BLOCKS  592
#define CONV_THREADS 256
#define TOTW (CONV_BLOCKS*(CONV_THREADS/32))   // 4736 warps

typedef unsigned long long u64;

// Scratch (static __device__ arrays: allocation-free).
__device__ int   g_grid[GRIDVOL];              // voxel -> point id, -1 empty
__device__ u64   g_wk2[NK * (CIN/2) * COUT];   // [k][ci2][co] packed f32x2
__device__ int   g_cnt[NBIN];
__device__ int2  g_pairs[(long)NBIN * NCAP];   // (in_idx, out_idx)
__device__ float g_acc[(long)NPTMAX * COUT];   // off-center accumulation buffer

// ---------------------------------------------------------------------------
// Packed f32x2 helpers (sm_103a FFMA2 path).
__device__ __forceinline__ u64 fma2(u64 a, u64 b, u64 c) {
    u64 d; asm("fma.rn.f32x2 %0, %1, %2, %3;" : "=l"(d) : "l"(a), "l"(b), "l"(c));
    return d;
}
__device__ __forceinline__ u64 mul2(u64 a, u64 b) {
    u64 d; asm("mul.rn.f32x2 %0, %1, %2;" : "=l"(d) : "l"(a), "l"(b));
    return d;
}
__device__ __forceinline__ u64 add2(u64 a, u64 b) {
    u64 d; asm("add.rn.f32x2 %0, %1, %2;" : "=l"(d) : "l"(a), "l"(b));
    return d;
}
__device__ __forceinline__ float hsum2(u64 a) {
    unsigned lo, hi;
    asm("mov.b64 {%0, %1}, %2;" : "=r"(lo), "=r"(hi) : "l"(a));
    return __uint_as_float(lo) + __uint_as_float(hi);
}

// 16-channel dot product, packed: f = 4 x ulonglong2 (16 floats), w = 8 x u64.
__device__ __forceinline__ float dot16p(const ulonglong2& f0, const ulonglong2& f1,
                                        const ulonglong2& f2, const ulonglong2& f3,
                                        const u64* w) {
    u64 s0 = mul2(f0.x, w[0]);
    u64 s1 = mul2(f0.y, w[1]);
    s0 = fma2(f1.x, w[2], s0);
    s1 = fma2(f1.y, w[3], s1);
    s0 = fma2(f2.x, w[4], s0);
    s1 = fma2(f2.y, w[5], s1);
    s0 = fma2(f3.x, w[6], s0);
    s1 = fma2(f3.y, w[7], s1);
    return hsum2(add2(s0, s1));
}

// ---------------------------------------------------------------------------
__global__ void scatter_idx_kernel(const int4* __restrict__ idx, int n) {
    int p = blockIdx.x * blockDim.x + threadIdx.x;
    if (p < n) {
        int4 q = idx[p];  // b, z, y, x
        g_grid[((q.x * DD + q.y) * HH + q.z) * WW + q.w] = p;
    }
}

// conv_w [co][ci][kd][kh][kw] -> g_wk2[k][ci2][co]; also zeroes bin counters.
__global__ void repack_w_kernel(const float* __restrict__ w) {
    int t = blockIdx.x * blockDim.x + threadIdx.x;
    if (blockIdx.x == 0 && threadIdx.x < NBIN) g_cnt[threadIdx.x] = 0;
    if (t < NK * (CIN/2) * COUT) {
        int k   = t / ((CIN/2) * COUT);
        int r   = t % ((CIN/2) * COUT);
        int ci2 = r / COUT;
        int co  = r % COUT;
        float w0 = w[(co * CIN + 2*ci2    ) * NK + k];
        float w1 = w[(co * CIN + 2*ci2 + 1) * NK + k];
        g_wk2[t] = ((u64)__float_as_uint(w1) << 32) | __float_as_uint(w0);
    }
}

// ---------------------------------------------------------------------------
// Build 26 off-center pair lists (smem staging, one aggregated global
// atomic per bin per block).
__global__ __launch_bounds__(256)
void probe_kernel(const int4* __restrict__ idx, int n) {
    __shared__ int  scnt[NBIN];
    __shared__ int  sbase[NBIN];
    __shared__ int2 srec[NBIN * CHUNK];

    int tid = threadIdx.x, lane = tid & 31, warp = tid >> 5;
    if (tid < NBIN) scnt[tid] = 0;
    __syncthreads();

    int kk = lane < 13 ? lane : lane + 1;
    int dz = kk / 9 - 1, dy = (kk / 3) % 3 - 1, dx = kk % 3 - 1;
    int p0 = blockIdx.x * CHUNK + warp * (CHUNK / 8);

#pragma unroll
    for (int r = 0; r < CHUNK / 8; r++) {
        int p = p0 + r;
        if (p < n && lane < NBIN) {
            int4 q = __ldg(&idx[p]);
            int zz = q.y + dz, yy = q.z + dy, xx = q.w + dx;
            if ((unsigned)zz < (unsigned)DD &&
                (unsigned)yy < (unsigned)HH &&
                (unsigned)xx < (unsigned)WW) {
                int j = __ldg(&g_grid[((q.x * DD + zz) * HH + yy) * WW + xx]);
                if (j >= 0) {
                    int pos = atomicAdd(&scnt[lane], 1);
                    srec[lane * CHUNK + pos] = make_int2(j, p);
                }
            }
        }
    }
    __syncthreads();
    if (tid < NBIN) sbase[tid] = atomicAdd(&g_cnt[tid], scnt[tid]);
    __syncthreads();
    for (int t = tid; t < NBIN * CHUNK; t += 256) {
        int b = t / CHUNK, i = t % CHUNK;
        if (i < scnt[b]) {
            int s = sbase[b] + i;
            if (s < NCAP) g_pairs[(long)b * NCAP + s] = srec[t];
        }
    }
}

// ---------------------------------------------------------------------------
// Pair conv: warp pinned to one bin; W_k packed in registers; unroll x4.
// REDs into g_acc (zero-initialized) -> order-free, runs FIRST (absorbs the
// cold DRAM misses on feat while it has deep latency-hiding).
__global__ __launch_bounds__(256)
void pair_conv_kernel(const ulonglong2* __restrict__ feat2) {
    int lane = threadIdx.x & 31;
    int w = blockIdx.x * (CONV_THREADS / 32) + (threadIdx.x >> 5);
    int b = w % NBIN, slice = w / NBIN;
    int nwk = (TOTW - b + NBIN - 1) / NBIN;
    int kk = b < 13 ? b : b + 1;

    u64 wk[8];
#pragma unroll
    for (int i = 0; i < 8; i++) wk[i] = g_wk2[(kk * 8 + i) * COUT + lane];

    int cnt = min(g_cnt[b], NCAP);
    const int2* pr = g_pairs + (long)b * NCAP;
    int chunk = (cnt + nwk - 1) / nwk;
    int i0 = slice * chunk;
    int i1 = min(cnt, i0 + chunk);

    int i = i0;
    for (; i + 3 < i1; i += 4) {
        int2 r0 = __ldg(&pr[i]);
        int2 r1 = __ldg(&pr[i + 1]);
        int2 r2 = __ldg(&pr[i + 2]);
        int2 r3 = __ldg(&pr[i + 3]);
        const ulonglong2* fa = feat2 + ((long)r0.x << 2);
        const ulonglong2* fb = feat2 + ((long)r1.x << 2);
        const ulonglong2* fc = feat2 + ((long)r2.x << 2);
        const ulonglong2* fd = feat2 + ((long)r3.x << 2);
        ulonglong2 a0 = __ldg(fa), a1 = __ldg(fa + 1),
                   a2 = __ldg(fa + 2), a3 = __ldg(fa + 3);
        ulonglong2 e0 = __ldg(fb), e1 = __ldg(fb + 1),
                   e2 = __ldg(fb + 2), e3 = __ldg(fb + 3);
        ulonglong2 c0 = __ldg(fc), c1 = __ldg(fc + 1),
                   c2 = __ldg(fc + 2), c3 = __ldg(fc + 3);
        ulonglong2 g0 = __ldg(fd), g1 = __ldg(fd + 1),
                   g2 = __ldg(fd + 2), g3 = __ldg(fd + 3);
        float s0 = dot16p(a0, a1, a2, a3, wk);
        float s1 = dot16p(e0, e1, e2, e3, wk);
        float s2 = dot16p(c0, c1, c2, c3, wk);
        float s3 = dot16p(g0, g1, g2, g3, wk);
        atomicAdd(&g_acc[(long)r0.y * COUT + lane], s0);
        atomicAdd(&g_acc[(long)r1.y * COUT + lane], s1);
        atomicAdd(&g_acc[(long)r2.y * COUT + lane], s2);
        atomicAdd(&g_acc[(long)r3.y * COUT + lane], s3);
    }
    for (; i < i1; i++) {
        int2 r0 = __ldg(&pr[i]);
        const ulonglong2* fa = feat2 + ((long)r0.x << 2);
        ulonglong2 a0 = __ldg(fa), a1 = __ldg(fa + 1),
                   a2 = __ldg(fa + 2), a3 = __ldg(fa + 3);
        atomicAdd(&g_acc[(long)r0.y * COUT + lane], dot16p(a0, a1, a2, a3, wk));
    }
}

// ---------------------------------------------------------------------------
// Final: out = bias + W13*feat + acc. Pure L2-hot streaming, no atomics.
// 2 points per iteration.
__global__ __launch_bounds__(256)
void center_final_kernel(const ulonglong2* __restrict__ feat2,
                         const float* __restrict__ bias,
                         float* __restrict__ out, int n) {
    int lane = threadIdx.x & 31;
    int w = blockIdx.x * (CONV_THREADS / 32) + (threadIdx.x >> 5);
    u64 wk[8];
#pragma unroll
    for (int i = 0; i < 8; i++) wk[i] = g_wk2[(13 * 8 + i) * COUT + lane];
    float b0 = __ldg(&bias[lane]);

    int p = w * 2;
    const int stride = TOTW * 2;
    for (; p + 1 < n; p += stride) {
        const ulonglong2* fa = feat2 + ((long)p << 2);
        const ulonglong2* fb = fa + 4;
        ulonglong2 a0 = __ldg(fa),     a1 = __ldg(fa + 1),
                   a2 = __ldg(fa + 2), a3 = __ldg(fa + 3);
        ulonglong2 c0 = __ldg(fb),     c1 = __ldg(fb + 1),
                   c2 = __ldg(fb + 2), c3 = __ldg(fb + 3);
        float accA = g_acc[(long)p * COUT + lane];
        float accB = g_acc[(long)(p + 1) * COUT + lane];
        out[(long)p * COUT + lane]       = b0 + accA + dot16p(a0, a1, a2, a3, wk);
        out[(long)(p + 1) * COUT + lane] = b0 + accB + dot16p(c0, c1, c2, c3, wk);
    }
    if (p < n) {
        const ulonglong2* fa = feat2 + ((long)p << 2);
        ulonglong2 a0 = __ldg(fa),     a1 = __ldg(fa + 1),
                   a2 = __ldg(fa + 2), a3 = __ldg(fa + 3);
        out[(long)p * COUT + lane] =
            b0 + g_acc[(long)p * COUT + lane] + dot16p(a0, a1, a2, a3, wk);
    }
}

// ---------------------------------------------------------------------------
extern "C" void kernel_launch(void* const* d_in, const int* in_sizes, int n_in,
                              void* d_out, int out_size) {
    const float* feat = (const float*)d_in[0];   // [n,16] f32
    const int*   idx  = (const int*)d_in[1];     // [n,4]  i32
    const float* w    = (const float*)d_in[2];   // [32,16,3,3,3] f32
    const float* bias = (const float*)d_in[3];   // [32] f32
    int n = in_sizes[1] / 4;

    void* gptr = nullptr; cudaGetSymbolAddress(&gptr, g_grid);
    void* aptr = nullptr; cudaGetSymbolAddress(&aptr, g_acc);
    cudaMemsetAsync(gptr, 0xFF, sizeof(int) * (size_t)GRIDVOL);          // act 1
    cudaMemsetAsync(aptr, 0, sizeof(float) * (size_t)n * COUT);          // act 2

    scatter_idx_kernel<<<(n + 255) / 256, 256>>>((const int4*)idx, n);   // act 3
    repack_w_kernel<<<(NK * (CIN/2) * COUT + 255) / 256, 256>>>(w);      // act 4
    probe_kernel<<<(n + CHUNK - 1) / CHUNK, 256>>>((const int4*)idx, n); // act 5
    pair_conv_kernel<<<CONV_BLOCKS, CONV_THREADS>>>(
        (const ulonglong2*)feat);                                        // act 6 (profiled)
    center_final_kernel<<<CONV_BLOCKS, CONV_THREADS>>>(
        (const ulonglong2*)feat, bias, (float*)d_out, n);                // act 7
}